// round 4
// baseline (speedup 1.0000x reference)
#include <cuda_runtime.h>
#include <math.h>

#define BNH 32
#define LL  1024
#define DD  64
#define RR  129
#define TI  16
#define TJ  256
#define NT  256

// shared layout (float units):
//   q_s   [16][64]      @ 0       (1024)
//   av_s  [16][132]     @ 1024    (2112)   qe in phases A/B, av afterwards
//   posi  [16] int      @ 3136
//   posa  [1024] int    @ 3152
//   p_s   [16][1024]    @ 4176    (16384)  scores -> probs -> partials
//   G                   @ 20560   (17408)  k-tile[256][68] / av64[16][132] u64 / v-tile[128][68]
//   emb_s [129][68]     @ 37968   (8772)   emb_k in phase A, emb_v afterwards
#define SMEM_FLOATS 46740
#define SMEM_BYTES  (SMEM_FLOATS * 4)

#define FIX_SCALE 4503599627370496.0f   /* 2^52 */
#define FIX_INV   (1.0f / 4503599627370496.0f)

extern "C" __global__ void __launch_bounds__(NT, 1)
attn_rel_kernel(const float* __restrict__ gq, const float* __restrict__ gk,
                const float* __restrict__ gv, const float* __restrict__ gw,
                const float* __restrict__ gek, const float* __restrict__ gev,
                const int* __restrict__ gpos, const unsigned char* __restrict__ gmask,
                float* __restrict__ gout, float* __restrict__ gp)
{
    extern __shared__ float sm[];
    float* q_s   = sm;
    float* av_s  = sm + 1024;
    int*   posi  = (int*)(sm + 3136);
    int*   posa  = (int*)(sm + 3152);
    float* p_s   = sm + 4176;
    float* G     = sm + 20560;
    float* emb_s = sm + 37968;

    const int b    = blockIdx.y;
    const int i0   = blockIdx.x * TI;
    const int tid  = threadIdx.x;
    const int lane = tid & 31;
    const int warp = tid >> 5;
    const unsigned FULL = 0xffffffffu;

    // ---------------- loads: q tile, pos, emb_k ----------------
    {
        const float4* q4 = (const float4*)(gq + ((size_t)b * LL + i0) * DD);
        ((float4*)q_s)[tid] = q4[tid];                 // 256 * float4 = 16x64
        if (tid < TI) posi[tid] = gpos[b * LL + i0 + tid];
        #pragma unroll
        for (int t = tid; t < LL; t += NT) posa[t] = gpos[b * LL + t];
        for (int e = tid; e < RR * DD; e += NT) {
            int r = e >> 6, d = e & 63;
            emb_s[r * 68 + d] = gek[e];
        }
    }
    __syncthreads();

    // ---------------- phase A: qe[i][r] = q[i] . emb_k[r] ----------------
    for (int e = tid; e < TI * RR; e += NT) {
        int i = e / RR, r = e - i * RR;
        const float4* qa = (const float4*)(q_s + i * DD);
        const float4* ea = (const float4*)(emb_s + r * 68);
        float acc = 0.f;
        #pragma unroll
        for (int c = 0; c < 16; c++) {
            float4 a = qa[c], e2 = ea[c];
            acc += a.x*e2.x + a.y*e2.y + a.z*e2.z + a.w*e2.w;
        }
        av_s[i * 132 + r] = acc;
    }
    __syncthreads();

    // ---------------- phase B: scores = (QK^T + qe[table] + attn_w)/8, mask ----------------
    const int ig = tid >> 6;      // 0..3  -> i in {ig, ig+4, ig+8, ig+12}
    const int jl = tid & 63;      // 0..63 -> j in {jl, jl+64, jl+128, jl+192} within tile
    for (int jt = 0; jt < LL / TJ; jt++) {
        {   // load k tile [256][64] -> G stride 68
            const float4* k4 = (const float4*)(gk + ((size_t)b * LL + jt * TJ) * DD);
            #pragma unroll
            for (int f = tid; f < TJ * (DD/4); f += NT) {
                int j = f >> 4, d4 = f & 15;
                *(float4*)(G + j * 68 + d4 * 4) = k4[f];
            }
        }
        __syncthreads();

        float acc[4][4];
        #pragma unroll
        for (int a = 0; a < 4; a++)
            #pragma unroll
            for (int c = 0; c < 4; c++) acc[a][c] = 0.f;

        #pragma unroll
        for (int d4 = 0; d4 < 16; d4++) {
            float4 qq[4], kk[4];
            #pragma unroll
            for (int a = 0; a < 4; a++)
                qq[a] = *(const float4*)(q_s + (ig + 4*a) * DD + d4 * 4);
            #pragma unroll
            for (int c = 0; c < 4; c++)
                kk[c] = *(const float4*)(G + (jl + 64*c) * 68 + d4 * 4);
            #pragma unroll
            for (int a = 0; a < 4; a++)
                #pragma unroll
                for (int c = 0; c < 4; c++)
                    acc[a][c] += qq[a].x*kk[c].x + qq[a].y*kk[c].y
                               + qq[a].z*kk[c].z + qq[a].w*kk[c].w;
        }

        #pragma unroll
        for (int a = 0; a < 4; a++) {
            int i  = ig + 4*a;
            int pi = posi[i];
            size_t rowoff = ((size_t)b * LL + (i0 + i)) * LL;
            #pragma unroll
            for (int c = 0; c < 4; c++) {
                int j = jt * TJ + jl + 64*c;
                int diff = posa[j] - pi;
                diff = max(-64, min(64, diff));
                float s = acc[a][c] + av_s[i * 132 + diff + 64] + gw[rowoff + j];
                s *= 0.125f;
                if (gmask[rowoff + j]) s = -INFINITY;
                p_s[i * 1024 + j] = s;
            }
        }
        __syncthreads();
    }

    // swap emb_k -> emb_v (not read until the final out stage; syncs below cover it)
    for (int e = tid; e < RR * DD; e += NT) {
        int r = e >> 6, d = e & 63;
        emb_s[r * 68 + d] = gev[e];
    }

    // ---------------- phase C: softmax + p write + av scatter (fixed-point, deterministic) ----------------
    for (int i = warp * 2; i < warp * 2 + 2; i++) {
        float* row = p_s + i * 1024;
        float m = -INFINITY;
        #pragma unroll
        for (int c = 0; c < 32; c++) m = fmaxf(m, row[lane + 32*c]);
        #pragma unroll
        for (int o = 16; o > 0; o >>= 1) m = fmaxf(m, __shfl_xor_sync(FULL, m, o));

        float sum = 0.f;
        #pragma unroll
        for (int c = 0; c < 32; c++) {
            float e = expf(row[lane + 32*c] - m);
            row[lane + 32*c] = e;
            sum += e;
        }
        #pragma unroll
        for (int o = 16; o > 0; o >>= 1) sum += __shfl_xor_sync(FULL, sum, o);

        size_t prow = ((size_t)b * LL + (i0 + i)) * LL;
        #pragma unroll
        for (int c = 0; c < 32; c++) {
            float pv = row[lane + 32*c] / sum;
            row[lane + 32*c] = pv;
            if (gp) gp[prow + lane + 32*c] = pv;
        }

        // direct scatter-add of p into 129 rel-pos buckets, exactly as the
        // reference does (same clip arithmetic as the gather in phase B).
        // Fixed-point u64 atomics: exact integer addition -> order-independent
        // -> deterministic across graph replays.
        unsigned long long* a64 = (unsigned long long*)G + (size_t)i * 132;
        for (int idx = lane; idx < 132; idx += 32) a64[idx] = 0ull;
        __syncwarp();

        int pi = posi[i];
        #pragma unroll
        for (int c = 0; c < 32; c++) {
            int j = lane + 32*c;
            int diff = posa[j] - pi;
            diff = max(-64, min(64, diff));
            unsigned long long qv = (unsigned long long)(row[j] * FIX_SCALE);
            atomicAdd(a64 + diff + 64, qv);
        }
        __syncwarp();

        #pragma unroll
        for (int c = 0; c < 5; c++) {
            int idx = lane + 32*c;
            if (idx < RR)
                av_s[i * 132 + idx] = __ull2float_rn(a64[idx]) * FIX_INV;
        }
        __syncwarp();
    }
    __syncthreads();

    // ---------------- phase D: out = P @ V  (j-partitioned) ----------------
    const int part = tid >> 6;               // 0..3: j-partition
    const int o64  = tid & 63;
    const int ig2  = o64 >> 4;                // i in {ig2, ig2+4, ig2+8, ig2+12}
    const int d4   = (o64 & 15) * 4;          // 4 consecutive d
    float4 acc2[4];
    #pragma unroll
    for (int c = 0; c < 4; c++) acc2[c] = make_float4(0.f, 0.f, 0.f, 0.f);

    for (int jt = 0; jt < 8; jt++) {
        {   // load v tile [128][64] -> G stride 68
            const float4* v4 = (const float4*)(gv + ((size_t)b * LL + jt * 128) * DD);
            #pragma unroll
            for (int f = tid; f < 128 * 16; f += NT) {
                int j = f >> 4, dd2 = f & 15;
                *(float4*)(G + j * 68 + dd2 * 4) = v4[f];
            }
        }
        __syncthreads();
        #pragma unroll 4
        for (int jj = 0; jj < 32; jj++) {
            int jloc = part * 32 + jj;
            int jg = jt * 128 + jloc;
            float4 vv = *(const float4*)(G + jloc * 68 + d4);
            #pragma unroll
            for (int c = 0; c < 4; c++) {
                float pp = p_s[(ig2 + 4*c) * 1024 + jg];
                acc2[c].x += pp * vv.x;
                acc2[c].y += pp * vv.y;
                acc2[c].z += pp * vv.z;
                acc2[c].w += pp * vv.w;
            }
        }
        __syncthreads();
    }

    // write partials into p_s (free now), reduce 4 partitions, add av @ emb_v
    #pragma unroll
    for (int c = 0; c < 4; c++)
        *(float4*)(p_s + part * 1024 + (ig2 + 4*c) * 64 + d4) = acc2[c];
    __syncthreads();

    if (gout) {
        #pragma unroll
        for (int c = 0; c < 4; c++) {
            int o = tid + 256 * c;            // 0..1023
            int i = o >> 6, d = o & 63;
            float s = p_s[o] + p_s[1024 + o] + p_s[2048 + o] + p_s[3072 + o];
            const float* avr = av_s + i * 132;
            const float* er  = emb_s + d;
            float s2 = 0.f;
            #pragma unroll 8
            for (int r = 0; r < RR; r++) s2 += avr[r] * er[r * 68];
            gout[((size_t)b * LL + i0 + i) * DD + d] = s + s2;
        }
    }
}

extern "C" void kernel_launch(void* const* d_in, const int* in_sizes, int n_in,
                              void* d_out, int out_size)
{
    const float* q   = (const float*)d_in[0];
    const float* k   = (const float*)d_in[1];
    const float* v   = (const float*)d_in[2];
    const float* w   = (const float*)d_in[3];
    const float* ek  = (const float*)d_in[4];
    const float* ev  = (const float*)d_in[5];
    const int*   pos = (const int*)d_in[6];
    const unsigned char* mask = (const unsigned char*)d_in[7];

    const long OUT_N = (long)BNH * LL * DD;   // 2,097,152
    const long P_N   = (long)BNH * LL * LL;   // 33,554,432

    float* outp = nullptr;
    float* pp   = nullptr;
    if ((long)out_size == OUT_N) {
        outp = (float*)d_out;
    } else if ((long)out_size == P_N) {
        pp = (float*)d_out;
    } else {
        outp = (float*)d_out;
        pp   = (float*)d_out + OUT_N;
    }

    cudaFuncSetAttribute(attn_rel_kernel,
                         cudaFuncAttributeMaxDynamicSharedMemorySize, SMEM_BYTES);
    dim3 grid(LL / TI, BNH);
    attn_rel_kernel<<<grid, NT, SMEM_BYTES>>>(q, k, v, w, ek, ev, pos, mask, outp, pp);
}

// round 5
// speedup vs baseline: 2.4262x; 2.4262x over previous
#include <cuda_runtime.h>
#include <math.h>

#define BNH 32
#define LL  1024
#define DD  64
#define RR  129
#define TI  16
#define TJ  256
#define NT  512

// shared layout (float units):
//   q_s   [16][64]      @ 0       (1024)
//   av_s  [16][132]     @ 1024    (2112)   qe in phases A/B, av afterwards
//   posi  [16] int      @ 3136
//   posa  [1024] int    @ 3152
//   p_s   [16][1024]    @ 4176    (16384)  scores -> probs -> partials
//   G                   @ 20560   (17408)  k-tile[256][68] / a64[16][132][4] u64 / v-tile[128][68]
//   emb_s [129][68]     @ 37968   (8772)   emb_k in phase A, emb_v afterwards
#define SMEM_FLOATS 46740
#define SMEM_BYTES  (SMEM_FLOATS * 4)

#define FIX_SCALE 4503599627370496.0f   /* 2^52 */
#define FIX_INV   (1.0f / 4503599627370496.0f)

extern "C" __global__ void __launch_bounds__(NT, 1)
attn_rel_kernel(const float* __restrict__ gq, const float* __restrict__ gk,
                const float* __restrict__ gv, const float* __restrict__ gw,
                const float* __restrict__ gek, const float* __restrict__ gev,
                const int* __restrict__ gpos, const unsigned char* __restrict__ gmask,
                float* __restrict__ gout, float* __restrict__ gp)
{
    extern __shared__ float sm[];
    float* q_s   = sm;
    float* av_s  = sm + 1024;
    int*   posi  = (int*)(sm + 3136);
    int*   posa  = (int*)(sm + 3152);
    float* p_s   = sm + 4176;
    float* G     = sm + 20560;
    float* emb_s = sm + 37968;

    const int b    = blockIdx.y;
    const int i0   = blockIdx.x * TI;
    const int tid  = threadIdx.x;
    const int lane = tid & 31;
    const int warp = tid >> 5;
    const unsigned FULL = 0xffffffffu;

    // ---------------- loads: q tile, pos, emb_k ----------------
    {
        if (tid < 256) {
            const float4* q4 = (const float4*)(gq + ((size_t)b * LL + i0) * DD);
            ((float4*)q_s)[tid] = q4[tid];             // 256 * float4 = 16x64
        }
        if (tid < TI) posi[tid] = gpos[b * LL + i0 + tid];
        #pragma unroll
        for (int t = tid; t < LL; t += NT) posa[t] = gpos[b * LL + t];
        for (int e = tid; e < RR * DD; e += NT) {
            int r = e >> 6, d = e & 63;
            emb_s[r * 68 + d] = gek[e];
        }
    }
    __syncthreads();

    // ---------------- phase A: qe[i][r] = q[i] . emb_k[r] ----------------
    for (int e = tid; e < TI * RR; e += NT) {
        int i = e / RR, r = e - i * RR;
        const float4* qa = (const float4*)(q_s + i * DD);
        const float4* ea = (const float4*)(emb_s + r * 68);
        float acc = 0.f;
        #pragma unroll
        for (int c = 0; c < 16; c++) {
            float4 a = qa[c], e2 = ea[c];
            acc += a.x*e2.x + a.y*e2.y + a.z*e2.z + a.w*e2.w;
        }
        av_s[i * 132 + r] = acc;
    }
    __syncthreads();

    // ---------------- phase B: scores = (QK^T + qe[table] + attn_w)/8, mask ----------------
    const int ig = tid >> 7;      // 0..3  -> i in {ig, ig+4, ig+8, ig+12}
    const int jl = tid & 127;     // 0..127 -> j in {jl, jl+128} within 256-tile
    for (int jt = 0; jt < LL / TJ; jt++) {
        {   // load k tile [256][64] -> G stride 68
            const float4* k4 = (const float4*)(gk + ((size_t)b * LL + jt * TJ) * DD);
            #pragma unroll
            for (int f = tid; f < TJ * (DD/4); f += NT) {
                int j = f >> 4, d4 = f & 15;
                *(float4*)(G + j * 68 + d4 * 4) = k4[f];
            }
        }
        __syncthreads();

        float acc[4][2];
        #pragma unroll
        for (int a = 0; a < 4; a++)
            #pragma unroll
            for (int c = 0; c < 2; c++) acc[a][c] = 0.f;

        #pragma unroll
        for (int d4 = 0; d4 < 16; d4++) {
            float4 qq[4], kk[2];
            #pragma unroll
            for (int a = 0; a < 4; a++)
                qq[a] = *(const float4*)(q_s + (ig + 4*a) * DD + d4 * 4);
            #pragma unroll
            for (int c = 0; c < 2; c++)
                kk[c] = *(const float4*)(G + (jl + 128*c) * 68 + d4 * 4);
            #pragma unroll
            for (int a = 0; a < 4; a++)
                #pragma unroll
                for (int c = 0; c < 2; c++)
                    acc[a][c] += qq[a].x*kk[c].x + qq[a].y*kk[c].y
                               + qq[a].z*kk[c].z + qq[a].w*kk[c].w;
        }

        #pragma unroll
        for (int a = 0; a < 4; a++) {
            int i  = ig + 4*a;
            int pi = posi[i];
            size_t rowoff = ((size_t)b * LL + (i0 + i)) * LL;
            #pragma unroll
            for (int c = 0; c < 2; c++) {
                int j = jt * TJ + jl + 128*c;
                int diff = posa[j] - pi;
                diff = max(-64, min(64, diff));
                float s = acc[a][c] + av_s[i * 132 + diff + 64] + gw[rowoff + j];
                s *= 0.125f;
                if (gmask[rowoff + j]) s = -INFINITY;
                p_s[i * 1024 + j] = s;
            }
        }
        __syncthreads();
    }

    // swap emb_k -> emb_v (not read until the final out stage; syncs below cover it)
    for (int e = tid; e < RR * DD; e += NT) {
        int r = e >> 6, d = e & 63;
        emb_s[r * 68 + d] = gev[e];
    }

    // ---------------- phase C: softmax + p write + av scatter (fixed-point, 4 banks) ----------------
    {
        const int i = warp;                     // 16 warps, one row each
        float* row = p_s + i * 1024;
        float m = -INFINITY;
        #pragma unroll
        for (int c = 0; c < 32; c++) m = fmaxf(m, row[lane + 32*c]);
        #pragma unroll
        for (int o = 16; o > 0; o >>= 1) m = fmaxf(m, __shfl_xor_sync(FULL, m, o));

        float sum = 0.f;
        #pragma unroll
        for (int c = 0; c < 32; c++) {
            float e = __expf(row[lane + 32*c] - m);
            row[lane + 32*c] = e;
            sum += e;
        }
        #pragma unroll
        for (int o = 16; o > 0; o >>= 1) sum += __shfl_xor_sync(FULL, sum, o);
        float inv = 1.0f / sum;

        size_t prow = ((size_t)b * LL + (i0 + i)) * LL;
        #pragma unroll
        for (int c = 0; c < 32; c++) {
            float pv = row[lane + 32*c] * inv;
            row[lane + 32*c] = pv;
            if (gp) gp[prow + lane + 32*c] = pv;
        }

        // fixed-point scatter into 129 buckets, 4 banks per bucket to cut
        // atomic conflicts 4x; integer adds are exact -> deterministic.
        unsigned long long* a64 = (unsigned long long*)G + (size_t)i * 528;
        for (int idx = lane; idx < 528; idx += 32) a64[idx] = 0ull;
        __syncwarp();

        int pi = posi[i];
        const int bank = lane & 3;
        #pragma unroll
        for (int c = 0; c < 32; c++) {
            int j = lane + 32*c;
            int diff = posa[j] - pi;
            diff = max(-64, min(64, diff));
            unsigned long long qv = (unsigned long long)(row[j] * FIX_SCALE);
            atomicAdd(a64 + (diff + 64) * 4 + bank, qv);
        }
        __syncwarp();

        #pragma unroll
        for (int c = 0; c < 5; c++) {
            int idx = lane + 32*c;
            if (idx < RR) {
                unsigned long long t = a64[idx*4] + a64[idx*4+1]
                                     + a64[idx*4+2] + a64[idx*4+3];
                av_s[i * 132 + idx] = __ull2float_rn(t) * FIX_INV;
            }
        }
    }
    __syncthreads();

    // ---------------- phase D: out = P @ V  (8 j-partitions) ----------------
    const int part = tid >> 6;                // 0..7: j-partition
    const int o64  = tid & 63;
    const int ig2  = o64 >> 4;                // i in {ig2, ig2+4, ig2+8, ig2+12}
    const int d4   = (o64 & 15) * 4;          // 4 consecutive d
    float4 acc2[4];
    #pragma unroll
    for (int c = 0; c < 4; c++) acc2[c] = make_float4(0.f, 0.f, 0.f, 0.f);

    for (int jt = 0; jt < 8; jt++) {
        {   // load v tile [128][64] -> G stride 68
            const float4* v4 = (const float4*)(gv + ((size_t)b * LL + jt * 128) * DD);
            #pragma unroll
            for (int f = tid; f < 128 * 16; f += NT) {
                int j = f >> 4, dd2 = f & 15;
                *(float4*)(G + j * 68 + dd2 * 4) = v4[f];
            }
        }
        __syncthreads();
        #pragma unroll
        for (int jj = 0; jj < 16; jj++) {
            int jloc = part * 16 + jj;
            int jg = jt * 128 + jloc;
            float4 vv = *(const float4*)(G + jloc * 68 + d4);
            #pragma unroll
            for (int c = 0; c < 4; c++) {
                float pp = p_s[(ig2 + 4*c) * 1024 + jg];
                acc2[c].x += pp * vv.x;
                acc2[c].y += pp * vv.y;
                acc2[c].z += pp * vv.z;
                acc2[c].w += pp * vv.w;
            }
        }
        __syncthreads();
    }

    // write partials into p_s (free now), reduce 8 partitions, add av @ emb_v
    #pragma unroll
    for (int c = 0; c < 4; c++)
        *(float4*)(p_s + part * 1024 + (ig2 + 4*c) * 64 + d4) = acc2[c];
    __syncthreads();

    if (gout) {
        #pragma unroll
        for (int c = 0; c < 2; c++) {
            int o = tid + 512 * c;            // 0..1023
            int i = o >> 6, d = o & 63;
            float s = 0.f;
            #pragma unroll
            for (int pt = 0; pt < 8; pt++) s += p_s[pt * 1024 + o];
            const float* avr = av_s + i * 132;
            const float* er  = emb_s + d;
            float s2 = 0.f;
            #pragma unroll 8
            for (int r = 0; r < RR; r++) s2 += avr[r] * er[r * 68];
            gout[((size_t)b * LL + i0 + i) * DD + d] = s + s2;
        }
    }
}

extern "C" void kernel_launch(void* const* d_in, const int* in_sizes, int n_in,
                              void* d_out, int out_size)
{
    const float* q   = (const float*)d_in[0];
    const float* k   = (const float*)d_in[1];
    const float* v   = (const float*)d_in[2];
    const float* w   = (const float*)d_in[3];
    const float* ek  = (const float*)d_in[4];
    const float* ev  = (const float*)d_in[5];
    const int*   pos = (const int*)d_in[6];
    const unsigned char* mask = (const unsigned char*)d_in[7];

    const long OUT_N = (long)BNH * LL * DD;   // 2,097,152
    const long P_N   = (long)BNH * LL * LL;   // 33,554,432

    float* outp = nullptr;
    float* pp   = nullptr;
    if ((long)out_size == OUT_N) {
        outp = (float*)d_out;
    } else if ((long)out_size == P_N) {
        pp = (float*)d_out;
    } else {
        outp = (float*)d_out;
        pp   = (float*)d_out + OUT_N;
    }

    cudaFuncSetAttribute(attn_rel_kernel,
                         cudaFuncAttributeMaxDynamicSharedMemorySize, SMEM_BYTES);
    dim3 grid(LL / TI, BNH);
    attn_rel_kernel<<<grid, NT, SMEM_BYTES>>>(q, k, v, w, ek, ev, pos, mask, outp, pp);
}

// round 6
// speedup vs baseline: 3.1111x; 1.2823x over previous
#include <cuda_runtime.h>
#include <math.h>

#define BNH 32
#define LL  1024
#define DD  64
#define RR  129
#define TI  16
#define TJ  256
#define NT  512

// shared layout (float units):
//   q_s   [16][68]      @ 0       (1088)   exact q (padded stride, frag loads conflict-free)
//   av_s  [16][132]     @ 1088    (2112)   qe in phases A/B, av afterwards
//   posi  [16] int      @ 3200
//   posa  [1024] int    @ 3216
//   p_s   [16][1032]    @ 4240    (16512)  scores -> p(exact->tf32) -> flat partials [2][1024]
//   G                   @ 20752   (18432)  k-tile[256][68] / a64[16][528] u64 / v-tile[256][72]
//   emb_s [129][68]     @ 39184   (8772)   emb_k in phase A, emb_v afterwards
#define SMEM_FLOATS 47956
#define SMEM_BYTES  (SMEM_FLOATS * 4)

#define PSTR 1032

#define FIX_SCALE 4503599627370496.0f   /* 2^52 */
#define FIX_INV   (1.0f / 4503599627370496.0f)

__device__ __forceinline__ unsigned tf32b(float x) {
    unsigned u;
    asm("cvt.rna.tf32.f32 %0, %1;" : "=r"(u) : "f"(x));
    return u;
}
__device__ __forceinline__ float tf32r(float x) { return __uint_as_float(tf32b(x)); }
__device__ __forceinline__ float4 tf32r4(float4 a) {
    a.x = tf32r(a.x); a.y = tf32r(a.y); a.z = tf32r(a.z); a.w = tf32r(a.w);
    return a;
}

#define MMA_TF32(c0,c1,c2,c3,a0,a1,a2,a3,b0,b1)                               \
    asm volatile("mma.sync.aligned.m16n8k8.row.col.f32.tf32.tf32.f32 "        \
                 "{%0,%1,%2,%3}, {%4,%5,%6,%7}, {%8,%9}, {%0,%1,%2,%3};"      \
                 : "+f"(c0), "+f"(c1), "+f"(c2), "+f"(c3)                      \
                 : "r"(a0), "r"(a1), "r"(a2), "r"(a3), "r"(b0), "r"(b1))

extern "C" __global__ void __launch_bounds__(NT, 1)
attn_rel_kernel(const float* __restrict__ gq, const float* __restrict__ gk,
                const float* __restrict__ gv, const float* __restrict__ gw,
                const float* __restrict__ gek, const float* __restrict__ gev,
                const int* __restrict__ gpos, const unsigned char* __restrict__ gmask,
                float* __restrict__ gout, float* __restrict__ gp)
{
    extern __shared__ float sm[];
    float* q_s   = sm;
    float* av_s  = sm + 1088;
    int*   posi  = (int*)(sm + 3200);
    int*   posa  = (int*)(sm + 3216);
    float* p_s   = sm + 4240;
    float* G     = sm + 20752;
    float* emb_s = sm + 39184;

    const int b    = blockIdx.y;
    const int i0   = blockIdx.x * TI;
    const int tid  = threadIdx.x;
    const int lane = tid & 31;
    const int warp = tid >> 5;
    const unsigned FULL = 0xffffffffu;

    const int gid  = lane >> 2;     // fragment "groupID" 0..7
    const int tid4 = lane & 3;      // fragment thread-in-group 0..3

    // ---------------- loads: q tile (exact, stride 68), pos, emb_k ----------------
    {
        if (tid < 256) {
            const float4* q4 = (const float4*)(gq + ((size_t)b * LL + i0) * DD);
            int row = tid >> 4, c4 = tid & 15;
            *(float4*)(q_s + row * 68 + c4 * 4) = q4[tid];
        }
        if (tid < TI) posi[tid] = gpos[b * LL + i0 + tid];
        #pragma unroll
        for (int t = tid; t < LL; t += NT) posa[t] = gpos[b * LL + t];
        for (int e = tid; e < RR * DD; e += NT) {
            int r = e >> 6, d = e & 63;
            emb_s[r * 68 + d] = gek[e];
        }
    }
    __syncthreads();

    // ---------------- phase A: qe[i][r] = q[i] . emb_k[r]  (exact fp32) ----------------
    for (int e = tid; e < TI * RR; e += NT) {
        int i = e / RR, r = e - i * RR;
        const float4* qa = (const float4*)(q_s + i * 68);
        const float4* ea = (const float4*)(emb_s + r * 68);
        float acc = 0.f;
        #pragma unroll
        for (int c = 0; c < 16; c++) {
            float4 a = qa[c], e2 = ea[c];
            acc += a.x*e2.x + a.y*e2.y + a.z*e2.z + a.w*e2.w;
        }
        av_s[i * 132 + r] = acc;
    }

    // build persistent tf32 A-fragments of q: af[kstep][0..3]
    unsigned af[8][4];
    #pragma unroll
    for (int ks = 0; ks < 8; ks++) {
        af[ks][0] = tf32b(q_s[ gid      * 68 + ks * 8 + tid4    ]);
        af[ks][1] = tf32b(q_s[(gid + 8) * 68 + ks * 8 + tid4    ]);
        af[ks][2] = tf32b(q_s[ gid      * 68 + ks * 8 + tid4 + 4]);
        af[ks][3] = tf32b(q_s[(gid + 8) * 68 + ks * 8 + tid4 + 4]);
    }
    __syncthreads();

    // ---------------- phase B: scores = (QK^T + qe[table] + attn_w)/8, mask ----------------
    // each warp owns 16 j columns per 256-j tile (2 n-tiles of 8)
    const int jbase = warp * 16;
    for (int jt = 0; jt < LL / TJ; jt++) {
        {   // load k tile [256][64] -> G stride 68, tf32-rounded
            const float4* k4 = (const float4*)(gk + ((size_t)b * LL + jt * TJ) * DD);
            #pragma unroll
            for (int f = tid; f < TJ * (DD/4); f += NT) {
                int j = f >> 4, d4 = f & 15;
                *(float4*)(G + j * 68 + d4 * 4) = tf32r4(k4[f]);
            }
        }
        __syncthreads();

        float c[2][4];
        #pragma unroll
        for (int t = 0; t < 2; t++)
            #pragma unroll
            for (int x = 0; x < 4; x++) c[t][x] = 0.f;

        #pragma unroll
        for (int ks = 0; ks < 8; ks++) {
            #pragma unroll
            for (int t = 0; t < 2; t++) {
                const float* kb = G + (jbase + t * 8 + gid) * 68 + ks * 8 + tid4;
                unsigned b0 = __float_as_uint(kb[0]);
                unsigned b1 = __float_as_uint(kb[4]);
                MMA_TF32(c[t][0], c[t][1], c[t][2], c[t][3],
                         af[ks][0], af[ks][1], af[ks][2], af[ks][3], b0, b1);
            }
        }

        // epilogue: add rel-pos gather + attn_w, scale, mask, store to p_s
        const int i_lo = gid, i_hi = gid + 8;
        const int pi_lo = posi[i_lo], pi_hi = posi[i_hi];
        const size_t row_lo = ((size_t)b * LL + (i0 + i_lo)) * LL;
        const size_t row_hi = ((size_t)b * LL + (i0 + i_hi)) * LL;
        #pragma unroll
        for (int t = 0; t < 2; t++) {
            int jg0 = jt * TJ + jbase + t * 8 + tid4 * 2;
            int pj0 = posa[jg0], pj1 = posa[jg0 + 1];
            int d00 = max(-64, min(64, pj0 - pi_lo)) + 64;
            int d01 = max(-64, min(64, pj1 - pi_lo)) + 64;
            int d10 = max(-64, min(64, pj0 - pi_hi)) + 64;
            int d11 = max(-64, min(64, pj1 - pi_hi)) + 64;
            float2 w_lo = *(const float2*)(gw + row_lo + jg0);
            float2 w_hi = *(const float2*)(gw + row_hi + jg0);
            uchar2 m_lo = *(const uchar2*)(gmask + row_lo + jg0);
            uchar2 m_hi = *(const uchar2*)(gmask + row_hi + jg0);
            float s00 = (c[t][0] + av_s[i_lo * 132 + d00] + w_lo.x) * 0.125f;
            float s01 = (c[t][1] + av_s[i_lo * 132 + d01] + w_lo.y) * 0.125f;
            float s10 = (c[t][2] + av_s[i_hi * 132 + d10] + w_hi.x) * 0.125f;
            float s11 = (c[t][3] + av_s[i_hi * 132 + d11] + w_hi.y) * 0.125f;
            if (m_lo.x) s00 = -INFINITY;
            if (m_lo.y) s01 = -INFINITY;
            if (m_hi.x) s10 = -INFINITY;
            if (m_hi.y) s11 = -INFINITY;
            *(float2*)(p_s + i_lo * PSTR + jg0) = make_float2(s00, s01);
            *(float2*)(p_s + i_hi * PSTR + jg0) = make_float2(s10, s11);
        }
        __syncthreads();
    }

    // swap emb_k -> emb_v (read only in the final out stage; syncs below cover it)
    for (int e = tid; e < RR * DD; e += NT) {
        int r = e >> 6, d = e & 63;
        emb_s[r * 68 + d] = gev[e];
    }

    // ---------------- phase C: softmax + p write + av scatter + tf32-round p ----------------
    {
        const int i = warp;                     // 16 warps, one row each
        float* row = p_s + i * PSTR;
        float m = -INFINITY;
        #pragma unroll
        for (int c = 0; c < 32; c++) m = fmaxf(m, row[lane + 32*c]);
        #pragma unroll
        for (int o = 16; o > 0; o >>= 1) m = fmaxf(m, __shfl_xor_sync(FULL, m, o));

        float sum = 0.f;
        #pragma unroll
        for (int c = 0; c < 32; c++) {
            float e = __expf(row[lane + 32*c] - m);
            row[lane + 32*c] = e;
            sum += e;
        }
        #pragma unroll
        for (int o = 16; o > 0; o >>= 1) sum += __shfl_xor_sync(FULL, sum, o);
        float inv = 1.0f / sum;

        size_t prow = ((size_t)b * LL + (i0 + i)) * LL;
        #pragma unroll
        for (int c = 0; c < 32; c++) {
            float pv = row[lane + 32*c] * inv;
            row[lane + 32*c] = pv;
            if (gp) gp[prow + lane + 32*c] = pv;
        }

        // fixed-point scatter into 129 buckets, 4 banks per bucket (exact -> deterministic)
        unsigned long long* a64 = (unsigned long long*)G + (size_t)i * 528;
        for (int idx = lane; idx < 528; idx += 32) a64[idx] = 0ull;
        __syncwarp();

        int pi = posi[i];
        const int bank = lane & 3;
        #pragma unroll
        for (int c = 0; c < 32; c++) {
            int j = lane + 32*c;
            int diff = posa[j] - pi;
            diff = max(-64, min(64, diff));
            unsigned long long qv = (unsigned long long)(row[j] * FIX_SCALE);
            atomicAdd(a64 + (diff + 64) * 4 + bank, qv);
        }
        __syncwarp();

        #pragma unroll
        for (int c = 0; c < 5; c++) {
            int idx = lane + 32*c;
            if (idx < RR) {
                unsigned long long t = a64[idx*4] + a64[idx*4+1]
                                     + a64[idx*4+2] + a64[idx*4+3];
                av_s[i * 132 + idx] = __ull2float_rn(t) * FIX_INV;
            }
        }
        __syncwarp();

        // round p row to tf32 in place for the P@V mma (gp holds exact p)
        #pragma unroll
        for (int c = 0; c < 32; c++)
            row[lane + 32*c] = tf32r(row[lane + 32*c]);
    }
    __syncthreads();

    // ---------------- phase D: out = P @ V  (tf32 mma, k split in 2 halves) ----------------
    const int ntile = warp & 7;                 // d-block of 8
    const int kh    = warp >> 3;                // j-half within each 256-tile
    float cd0 = 0.f, cd1 = 0.f, cd2 = 0.f, cd3 = 0.f;

    for (int jt = 0; jt < 4; jt++) {
        {   // load v tile [256][64] -> G stride 72, tf32-rounded
            const float4* v4 = (const float4*)(gv + ((size_t)b * LL + jt * 256) * DD);
            #pragma unroll
            for (int f = tid; f < 256 * 16; f += NT) {
                int j = f >> 4, dd2 = f & 15;
                *(float4*)(G + j * 72 + dd2 * 4) = tf32r4(v4[f]);
            }
        }
        __syncthreads();

        #pragma unroll
        for (int ks = 0; ks < 16; ks++) {
            int jrow = kh * 128 + ks * 8;               // within tile
            int jcol = jt * 256 + jrow + tid4;          // global j
            unsigned a0 = __float_as_uint(p_s[ gid      * PSTR + jcol    ]);
            unsigned a1 = __float_as_uint(p_s[(gid + 8) * PSTR + jcol    ]);
            unsigned a2 = __float_as_uint(p_s[ gid      * PSTR + jcol + 4]);
            unsigned a3 = __float_as_uint(p_s[(gid + 8) * PSTR + jcol + 4]);
            const float* vb = G + (jrow + tid4) * 72 + ntile * 8 + gid;
            unsigned b0 = __float_as_uint(vb[0]);
            unsigned b1 = __float_as_uint(vb[4 * 72]);
            MMA_TF32(cd0, cd1, cd2, cd3, a0, a1, a2, a3, b0, b1);
        }
        __syncthreads();
    }

    // write the two k-half partials into p_s (flat [2][16][64]; p_s is free now)
    {
        int d0 = ntile * 8 + tid4 * 2;
        float* P = p_s + kh * 1024;
        *(float2*)(P +  gid      * 64 + d0) = make_float2(cd0, cd1);
        *(float2*)(P + (gid + 8) * 64 + d0) = make_float2(cd2, cd3);
    }
    __syncthreads();

    if (gout) {
        #pragma unroll
        for (int c = 0; c < 2; c++) {
            int o = tid + 512 * c;            // 0..1023
            int i = o >> 6, d = o & 63;
            float s = p_s[o] + p_s[1024 + o];
            const float* avr = av_s + i * 132;
            const float* er  = emb_s + d;
            float s2 = 0.f;
            #pragma unroll 8
            for (int r = 0; r < RR; r++) s2 += avr[r] * er[r * 68];
            gout[((size_t)b * LL + i0 + i) * DD + d] = s + s2;
        }
    }
}

extern "C" void kernel_launch(void* const* d_in, const int* in_sizes, int n_in,
                              void* d_out, int out_size)
{
    const float* q   = (const float*)d_in[0];
    const float* k   = (const float*)d_in[1];
    const float* v   = (const float*)d_in[2];
    const float* w   = (const float*)d_in[3];
    const float* ek  = (const float*)d_in[4];
    const float* ev  = (const float*)d_in[5];
    const int*   pos = (const int*)d_in[6];
    const unsigned char* mask = (const unsigned char*)d_in[7];

    const long OUT_N = (long)BNH * LL * DD;   // 2,097,152
    const long P_N   = (long)BNH * LL * LL;   // 33,554,432

    float* outp = nullptr;
    float* pp   = nullptr;
    if ((long)out_size == OUT_N) {
        outp = (float*)d_out;
    } else if ((long)out_size == P_N) {
        pp = (float*)d_out;
    } else {
        outp = (float*)d_out;
        pp   = (float*)d_out + OUT_N;
    }

    cudaFuncSetAttribute(attn_rel_kernel,
                         cudaFuncAttributeMaxDynamicSharedMemorySize, SMEM_BYTES);
    dim3 grid(LL / TI, BNH);
    attn_rel_kernel<<<grid, NT, SMEM_BYTES>>>(q, k, v, w, ek, ev, pos, mask, outp, pp);
}